// round 16
// baseline (speedup 1.0000x reference)
#include <cuda_runtime.h>
#include <cstdint>

// AntisymmetricRNN: x_{t+1} = x_t + 0.01*tanh(A x_t + by)
// A = triu(W,1) - triu(W,1)^T - eps*I.  N=256, BS=256, TMAX=1000.
// R16 = R15 core (136 triangle tiles in registers, 544 threads, GSTR=18 skew,
// 17 partial slots, fast tanh) + SOFTWARE PIPELINING of the two batch columns:
// each phase overlaps one column's GEMV compute with the other column's
// finalize chain (17 LDS + tanh + stores), hiding the serial latency that
// left R15 at 46% issue. Finalize ownership interleaved (c_out = tid&1) so
// both phases' finalize work spreads across all 16 owner warps.

constexpr int   Nn      = 256;
constexpr int   Tmax    = 1000;
constexpr float STEPF   = 0.01f;
constexpr float EPSF    = 0.001f;
constexpr int   THREADS = 544;            // 136 teams x 4 lanes = 17 warps

constexpr int   GSTR    = 18;             // floats per 16-row group (skew)
constexpr int   XCS     = 16 * GSTR + 8;  // 296: x column stride
constexpr int   PSS     = 272;            // partial slot stride
constexpr int   PCS     = 17 * PSS;       // 4624: partial column stride

constexpr int   OFF_X     = 0;            // 2*296 floats
constexpr int   OFF_PART  = 592;
constexpr int   SM_FLOATS = OFF_PART + 2 * PCS;   // 9840 floats

__device__ __forceinline__ void fma2(unsigned long long& d,
                                     unsigned long long a,
                                     unsigned long long b) {
    asm("fma.rn.f32x2 %0, %1, %2, %0;" : "+l"(d) : "l"(a), "l"(b));
}
__device__ __forceinline__ unsigned long long addx2(unsigned long long a,
                                                    unsigned long long b) {
    unsigned long long d;
    asm("add.rn.f32x2 %0, %1, %2;" : "=l"(d) : "l"(a), "l"(b));
    return d;
}
__device__ __forceinline__ unsigned long long pk2(float lo, float hi) {
    unsigned long long v;
    asm("mov.b64 %0, {%1, %2};" : "=l"(v) : "f"(lo), "f"(hi));
    return v;
}
__device__ __forceinline__ float2 upk2(unsigned long long v) {
    float2 r;
    asm("mov.b64 {%0, %1}, %2;" : "=f"(r.x), "=f"(r.y) : "l"(v));
    return r;
}
__device__ __forceinline__ float tval(const float* __restrict__ W, int i, int j) {
    return (j > i) ? W[i * Nn + j] : 0.0f;
}
__device__ __forceinline__ float fast_tanh(float y) {
    float e, r;
    asm("ex2.approx.ftz.f32 %0, %1;" : "=f"(e) : "f"(y * 2.8853900817779268f));
    asm("rcp.approx.ftz.f32 %0, %1;" : "=f"(r) : "f"(e + 1.0f));
    return fmaf(-2.0f, r, 1.0f);
}

__global__ void __launch_bounds__(THREADS, 1)
antisym_rnn_kernel(const float* __restrict__ X0,
                   const float* __restrict__ W,
                   const float* __restrict__ by,
                   float* __restrict__ out) {
    extern __shared__ float sm[];
    float* xs   = sm + OFF_X;
    float* part = sm + OFF_PART;

    const int tid = threadIdx.x;
    const int q   = tid & 3;
    const int bid = blockIdx.x;

    // ---- team -> tile (a, b), a <= b ----
    int a = 0, rem = tid >> 2;
    while (rem >= 16 - a) { rem -= 16 - a; ++a; }
    const int b = a + rem;
    const int tslot = (a == b) ? 16 : a;
    const int b0q = q & 1, b1q = (q >> 1) & 1;

    // ---- output ownership: interleaved so both phases use all 16 warps ----
    const bool has_out = tid < 512;
    const int  c_out   = tid & 1;               // column this thread finalizes
    const int  row_out = (tid >> 1) & 255;
    float x_own = 0.f, byv = 0.f;
    float* outp = nullptr;
    if (has_out) {
        byv   = by[row_out];
        x_own = X0[(size_t)(2 * bid + c_out) * Nn + row_out];
        outp  = out + ((size_t)(2 * bid + c_out) * Tmax) * Nn + row_out;
        outp[0] = x_own;
        xs[c_out * XCS + (row_out >> 4) * GSTR + (row_out & 15)] = x_own;
    }

    // ---- tile block in registers: 4 rows x 8 pairs ----
    unsigned long long A[4][8];
#pragma unroll
    for (int r = 0; r < 4; ++r) {
        const int i = a * 16 + 4 * q + r;
#pragma unroll
        for (int p = 0; p < 8; ++p) {
            const int j = b * 16 + 2 * p;
            A[r][p] = pk2(tval(W, i, j), tval(W, i, j + 1));
        }
    }

    // ---- per-column GEMV partials (fwd + negated transpose) ----
    auto compute_col = [&](int c) {
        const float* xc = xs + c * XCS;

        unsigned long long xq[8];
#pragma unroll
        for (int m8 = 0; m8 < 8; ++m8)
            xq[m8] = *reinterpret_cast<const unsigned long long*>(xc + b * GSTR + 2 * m8);

        unsigned long long accF[4] = {0ULL, 0ULL, 0ULL, 0ULL};
#pragma unroll
        for (int p = 0; p < 8; ++p) {
#pragma unroll
            for (int r = 0; r < 4; ++r) fma2(accF[r], A[r][p], xq[p]);
        }
        float4 fs;
        { const float2 f = upk2(accF[0]); fs.x = f.x + f.y; }
        { const float2 f = upk2(accF[1]); fs.y = f.x + f.y; }
        { const float2 f = upk2(accF[2]); fs.z = f.x + f.y; }
        { const float2 f = upk2(accF[3]); fs.w = f.x + f.y; }
        *reinterpret_cast<float4*>(part + c * PCS + b * PSS + a * 16 + 4 * q) = fs;

        const unsigned long long xo01 =
            *reinterpret_cast<const unsigned long long*>(xc + a * GSTR + 4 * q);
        const unsigned long long xo23 =
            *reinterpret_cast<const unsigned long long*>(xc + a * GSTR + 4 * q + 2);
        const float2 xo0 = upk2(xo01);
        const float2 xo1 = upk2(xo23);
        const float xr[4] = {xo0.x, xo0.y, xo1.x, xo1.y};

        unsigned long long accT[8] = {0ULL,0ULL,0ULL,0ULL,0ULL,0ULL,0ULL,0ULL};
#pragma unroll
        for (int r = 0; r < 4; ++r) {
            const unsigned long long nx = pk2(-xr[r], -xr[r]);
#pragma unroll
            for (int p = 0; p < 8; ++p) fma2(accT[p], A[r][p], nx);
        }

        unsigned long long sA[4];
#pragma unroll
        for (int k = 0; k < 4; ++k) {
            const unsigned long long keep = b1q ? accT[4 + k] : accT[k];
            const unsigned long long send = b1q ? accT[k]     : accT[4 + k];
            sA[k] = addx2(keep, __shfl_xor_sync(0xFFFFFFFFu, send, 2));
        }
        ulonglong2 ts;
        {
            const unsigned long long keep = b0q ? sA[2] : sA[0];
            const unsigned long long send = b0q ? sA[0] : sA[2];
            ts.x = addx2(keep, __shfl_xor_sync(0xFFFFFFFFu, send, 1));
        }
        {
            const unsigned long long keep = b0q ? sA[3] : sA[1];
            const unsigned long long send = b0q ? sA[1] : sA[3];
            ts.y = addx2(keep, __shfl_xor_sync(0xFFFFFFFFu, send, 1));
        }
        *reinterpret_cast<ulonglong2*>(part + c * PCS + tslot * PSS + b * 16 + 4 * q) = ts;
    };

    // ---- finalize own (c_out, row_out) output for step s ----
    auto finalize_col = [&](int s) {
        const float* pp = part + c_out * PCS + row_out;
        float y0 = byv - EPSF * x_own, y1 = 0.f, y2 = 0.f, y3 = 0.f;
#pragma unroll
        for (int sl = 0; sl < 16; sl += 4) {
            y0 += pp[(sl + 0) * PSS];
            y1 += pp[(sl + 1) * PSS];
            y2 += pp[(sl + 2) * PSS];
            y3 += pp[(sl + 3) * PSS];
        }
        const float y = (y0 + y1) + (y2 + y3) + pp[16 * PSS];
        x_own += STEPF * fast_tanh(y);
        outp[(size_t)s * Nn] = x_own;
        xs[c_out * XCS + (row_out >> 4) * GSTR + (row_out & 15)] = x_own;
    };

    __syncthreads();

    // ---- prologue: col0 partials for step 1 ----
    compute_col(0);
    __syncthreads();

    // ---- pipelined time loop: 2 phases/step, each = 1 col compute + 1 col finalize ----
    for (int s = 1; s < Tmax; ++s) {
        // phase A: compute col1 partials(s); finalize col0(s)
        compute_col(1);
        if (has_out && c_out == 0) finalize_col(s);
        __syncthreads();

        // phase B: compute col0 partials(s+1); finalize col1(s)
        if (s + 1 < Tmax) compute_col(0);
        if (has_out && c_out == 1) finalize_col(s);
        __syncthreads();
    }
}

extern "C" void kernel_launch(void* const* d_in, const int* in_sizes, int n_in,
                              void* d_out, int out_size) {
    const float* X0 = (const float*)d_in[0];
    const float* W  = (const float*)d_in[1];
    const float* by = (const float*)d_in[2];
    float* out      = (float*)d_out;

    const int smem_bytes = SM_FLOATS * 4;
    cudaFuncSetAttribute(antisym_rnn_kernel,
                         cudaFuncAttributeMaxDynamicSharedMemorySize, smem_bytes);
    antisym_rnn_kernel<<<128, THREADS, smem_bytes>>>(X0, W, by, out);
}